// round 2
// baseline (speedup 1.0000x reference)
#include <cuda_runtime.h>
#include <math.h>

#define BSZ 2
#define SEQ 2048
#define DIM 2048
#define NH 16
#define HDIM 128

// Scratch (device-global: no allocations allowed)
__device__ float g_q[BSZ * SEQ * DIM];    // [b,h,n,hd] head-major
__device__ float g_k[BSZ * SEQ * DIM];
__device__ float g_v[BSZ * SEQ * DIM];
__device__ float g_att[BSZ * SEQ * DIM];  // [b,n,h*hd] token-major

// ---------------------------------------------------------------------------
// C[m,n] = sum_k A[m,k] * W[n,k]   (A: MxK row-major, W: NxK row-major)
// 128x128 tile, BK=16, 256 threads, 8x8 per-thread microtile.
// headmajor: write C as [b, h, n, hd] instead of [m, n].
// ---------------------------------------------------------------------------
__global__ void __launch_bounds__(256) gemm_nt_kernel(
    const float* __restrict__ A, const float* __restrict__ W,
    float* __restrict__ C, int M, int Nn, int K, int headmajor)
{
    __shared__ float As[16][132];
    __shared__ float Bs[16][132];
    const int tid = threadIdx.x;
    const int bm = blockIdx.y * 128;
    const int bn = blockIdx.x * 128;
    const int ty = tid >> 4;        // 0..15
    const int tx = tid & 15;        // 0..15

    float acc[8][8];
#pragma unroll
    for (int i = 0; i < 8; i++)
#pragma unroll
        for (int j = 0; j < 8; j++) acc[i][j] = 0.f;

    const int lr = tid >> 2;        // 0..63
    const int lc = (tid & 3) << 2;  // 0,4,8,12
    const float* Ap = A + (size_t)(bm + lr) * K + lc;
    const float* Wp = W + (size_t)(bn + lr) * K + lc;

    for (int k0 = 0; k0 < K; k0 += 16) {
        float4 a0 = *(const float4*)(Ap + k0);
        float4 a1 = *(const float4*)(Ap + k0 + (size_t)64 * K);
        float4 b0 = *(const float4*)(Wp + k0);
        float4 b1 = *(const float4*)(Wp + k0 + (size_t)64 * K);
        __syncthreads();
        As[lc + 0][lr] = a0.x; As[lc + 1][lr] = a0.y; As[lc + 2][lr] = a0.z; As[lc + 3][lr] = a0.w;
        As[lc + 0][lr + 64] = a1.x; As[lc + 1][lr + 64] = a1.y; As[lc + 2][lr + 64] = a1.z; As[lc + 3][lr + 64] = a1.w;
        Bs[lc + 0][lr] = b0.x; Bs[lc + 1][lr] = b0.y; Bs[lc + 2][lr] = b0.z; Bs[lc + 3][lr] = b0.w;
        Bs[lc + 0][lr + 64] = b1.x; Bs[lc + 1][lr + 64] = b1.y; Bs[lc + 2][lr + 64] = b1.z; Bs[lc + 3][lr + 64] = b1.w;
        __syncthreads();
#pragma unroll
        for (int kk = 0; kk < 16; kk++) {
            float4 av0 = *(const float4*)&As[kk][ty * 8];
            float4 av1 = *(const float4*)&As[kk][ty * 8 + 4];
            float4 bv0 = *(const float4*)&Bs[kk][tx * 8];
            float4 bv1 = *(const float4*)&Bs[kk][tx * 8 + 4];
            float a[8] = {av0.x, av0.y, av0.z, av0.w, av1.x, av1.y, av1.z, av1.w};
            float b[8] = {bv0.x, bv0.y, bv0.z, bv0.w, bv1.x, bv1.y, bv1.z, bv1.w};
#pragma unroll
            for (int i = 0; i < 8; i++)
#pragma unroll
                for (int j = 0; j < 8; j++)
                    acc[i][j] = fmaf(a[i], b[j], acc[i][j]);
        }
    }

#pragma unroll
    for (int i = 0; i < 8; i++) {
        int m = bm + ty * 8 + i;
#pragma unroll
        for (int j = 0; j < 8; j++) {
            int n = bn + tx * 8 + j;
            size_t idx;
            if (headmajor) {
                int bi = m >> 11;     // m / SEQ
                int ni = m & (SEQ - 1);
                int hh = n >> 7;      // n / HDIM
                int t = n & (HDIM - 1);
                idx = ((((size_t)bi * NH + hh) * SEQ) + ni) * HDIM + t;
            } else {
                idx = (size_t)m * Nn + n;
            }
            C[idx] = acc[i][j];
        }
    }
}

// ---------------------------------------------------------------------------
// In-place RoPE on g_q, g_k (head-major [b,h,n,hd]).
// theta_t = 10000^(-t/64), pairs (t, t+64).
// ---------------------------------------------------------------------------
__global__ void rope_kernel()
{
    int idx = blockIdx.x * blockDim.x + threadIdx.x;  // total = BSZ*NH*SEQ*64
    int t = idx & 63;
    int ni = (idx >> 6) & (SEQ - 1);
    int bh = idx >> 17;  // 0..31
    size_t base = ((size_t)bh * SEQ + ni) * HDIM;

    // ln(10000)/64 = 0.14391156831
    float theta = expf((float)t * -0.14391156831f);
    float ang = (float)ni * theta;
    float s, c;
    sincosf(ang, &s, &c);

    float q1 = g_q[base + t], q2 = g_q[base + t + 64];
    g_q[base + t]      = q1 * c - q2 * s;
    g_q[base + t + 64] = q1 * s + q2 * c;
    float k1 = g_k[base + t], k2 = g_k[base + t + 64];
    g_k[base + t]      = k1 * c - k2 * s;
    g_k[base + t + 64] = k1 * s + k2 * c;
}

// ---------------------------------------------------------------------------
// Poly attention: per (b,h), scores = (q.k)^4 causal; out = scores@v / sum.
// Block = 32 queries; loop over 32-key tiles. 256 threads.
// Scores computed GEMM-style with transposed padded Q/K smem (conflict-free).
// Static smem (fits < 48KB):
//   Qts [128][33], Kts [128][33], Vs [32][128], Ss [32][33], Dsm [32]
//   = 8448 + 4096 + 1056 + 32 floats = 45.05 KB
// ---------------------------------------------------------------------------
__global__ void __launch_bounds__(256) attn_kernel(float* __restrict__ O)
{
    __shared__ float Qts[128 * 33];
    __shared__ float Kts[128 * 33];
    __shared__ float Vs[32 * 128];
    __shared__ float Ss[32 * 33];
    __shared__ float Dsm[32];

    const int tid = threadIdx.x;
    const int q0 = blockIdx.x * 32;
    const int h = blockIdx.y;
    const int bi = blockIdx.z;
    const size_t hb = (((size_t)bi * NH + h) * SEQ) * HDIM;
    const float* Qb = g_q + hb;
    const float* Kb = g_k + hb;
    const float* Vb = g_v + hb;

    // Load Q tile transposed into Qts[t][r]
    for (int i = tid; i < 32 * 32; i += 256) {
        int r = i >> 5;
        int c = (i & 31) << 2;
        float4 v = *(const float4*)(Qb + (size_t)(q0 + r) * HDIM + c);
        Qts[(c + 0) * 33 + r] = v.x;
        Qts[(c + 1) * 33 + r] = v.y;
        Qts[(c + 2) * 33 + r] = v.z;
        Qts[(c + 3) * 33 + r] = v.w;
    }

    const int ty = tid >> 4, tx = tid & 15;        // score microtile coords
    const int qi = tid & 31, dg = tid >> 5;        // AV coords
    const int d0 = dg << 4;

    float acc[16];
#pragma unroll
    for (int i = 0; i < 16; i++) acc[i] = 0.f;
    float denom = 0.f;

    const int nk = q0 + 32;  // causal: keys [0, q0+32)
    for (int j0 = 0; j0 < nk; j0 += 32) {
        __syncthreads();
        // Load K tile transposed + V tile row-major
        for (int i = tid; i < 32 * 32; i += 256) {
            int r = i >> 5;
            int c = (i & 31) << 2;
            float4 kv = *(const float4*)(Kb + (size_t)(j0 + r) * HDIM + c);
            Kts[(c + 0) * 33 + r] = kv.x;
            Kts[(c + 1) * 33 + r] = kv.y;
            Kts[(c + 2) * 33 + r] = kv.z;
            Kts[(c + 3) * 33 + r] = kv.w;
            *(float4*)(Vs + r * HDIM + c) =
                *(const float4*)(Vb + (size_t)(j0 + r) * HDIM + c);
        }
        __syncthreads();

        // Scores: 2x2 microtile per thread over [32q x 32k]
        float s00 = 0.f, s01 = 0.f, s10 = 0.f, s11 = 0.f;
        const int a0i = ty * 2, b0i = tx * 2;
#pragma unroll 8
        for (int t = 0; t < 128; t++) {
            float a0 = Qts[t * 33 + a0i];
            float a1 = Qts[t * 33 + a0i + 1];
            float b0 = Kts[t * 33 + b0i];
            float b1 = Kts[t * 33 + b0i + 1];
            s00 = fmaf(a0, b0, s00);
            s01 = fmaf(a0, b1, s01);
            s10 = fmaf(a1, b0, s10);
            s11 = fmaf(a1, b1, s11);
        }
        // ^4 + causal mask, store to Ss
        const int iq = q0 + a0i, jg = j0 + b0i;
        float p;
        p = s00 * s00; p = p * p; if (jg     > iq    ) p = 0.f; Ss[a0i * 33 + b0i]           = p;
        p = s01 * s01; p = p * p; if (jg + 1 > iq    ) p = 0.f; Ss[a0i * 33 + b0i + 1]       = p;
        p = s10 * s10; p = p * p; if (jg     > iq + 1) p = 0.f; Ss[(a0i + 1) * 33 + b0i]     = p;
        p = s11 * s11; p = p * p; if (jg + 1 > iq + 1) p = 0.f; Ss[(a0i + 1) * 33 + b0i + 1] = p;
        __syncthreads();

        // AV accumulation: thread -> (query qi, dims [d0, d0+16))
#pragma unroll
        for (int j = 0; j < 32; j++) {
            float s = Ss[qi * 33 + j];
            if (dg == 0) denom += s;
            float4 v0 = *(const float4*)(Vs + j * HDIM + d0);
            float4 v1 = *(const float4*)(Vs + j * HDIM + d0 + 4);
            float4 v2 = *(const float4*)(Vs + j * HDIM + d0 + 8);
            float4 v3 = *(const float4*)(Vs + j * HDIM + d0 + 12);
            acc[0]  = fmaf(s, v0.x, acc[0]);  acc[1]  = fmaf(s, v0.y, acc[1]);
            acc[2]  = fmaf(s, v0.z, acc[2]);  acc[3]  = fmaf(s, v0.w, acc[3]);
            acc[4]  = fmaf(s, v1.x, acc[4]);  acc[5]  = fmaf(s, v1.y, acc[5]);
            acc[6]  = fmaf(s, v1.z, acc[6]);  acc[7]  = fmaf(s, v1.w, acc[7]);
            acc[8]  = fmaf(s, v2.x, acc[8]);  acc[9]  = fmaf(s, v2.y, acc[9]);
            acc[10] = fmaf(s, v2.z, acc[10]); acc[11] = fmaf(s, v2.w, acc[11]);
            acc[12] = fmaf(s, v3.x, acc[12]); acc[13] = fmaf(s, v3.y, acc[13]);
            acc[14] = fmaf(s, v3.z, acc[14]); acc[15] = fmaf(s, v3.w, acc[15]);
        }
    }

    if (dg == 0) Dsm[qi] = denom;
    __syncthreads();
    float inv = 1.f / fmaxf(Dsm[qi], 1e-6f);

    // Write token-major [b, n, h*hd]
    float* Op = O + ((size_t)bi * SEQ + q0 + qi) * DIM + h * HDIM + d0;
#pragma unroll
    for (int i = 0; i < 16; i++) Op[i] = acc[i] * inv;
}

// ---------------------------------------------------------------------------
extern "C" void kernel_launch(void* const* d_in, const int* in_sizes, int n_in,
                              void* d_out, int out_size)
{
    const float* x  = (const float*)d_in[0];
    const float* Wq = (const float*)d_in[1];
    const float* Wk = (const float*)d_in[2];
    const float* Wv = (const float*)d_in[3];
    const float* Wo = (const float*)d_in[4];
    float* out = (float*)d_out;

    float *q, *k, *v, *att;
    cudaGetSymbolAddress((void**)&q, g_q);
    cudaGetSymbolAddress((void**)&k, g_k);
    cudaGetSymbolAddress((void**)&v, g_v);
    cudaGetSymbolAddress((void**)&att, g_att);

    const int M = BSZ * SEQ;  // 4096
    dim3 ggrid(DIM / 128, M / 128);  // (16, 32)

    gemm_nt_kernel<<<ggrid, 256>>>(x, Wq, q, M, DIM, DIM, 1);
    gemm_nt_kernel<<<ggrid, 256>>>(x, Wk, k, M, DIM, DIM, 1);
    gemm_nt_kernel<<<ggrid, 256>>>(x, Wv, v, M, DIM, DIM, 1);

    rope_kernel<<<(BSZ * NH * SEQ * 64) / 256, 256>>>();

    attn_kernel<<<dim3(SEQ / 32, NH, BSZ), 256>>>(att);

    gemm_nt_kernel<<<ggrid, 256>>>(att, Wo, out, M, DIM, DIM, 0);
}

// round 5
// speedup vs baseline: 1.8066x; 1.8066x over previous
#include <cuda_runtime.h>
#include <cuda_bf16.h>
#include <math.h>
#include <stdint.h>

#define BSZ 2
#define SEQ 2048
#define DIM 2048
#define NH 16
#define HDIM 128
#define MTOT (BSZ * SEQ)   // 4096

// ---------------- scratch (device globals; no allocs allowed) ---------------
__device__ float g_q[BSZ * SEQ * DIM];    // [b,h,n,hd]
__device__ float g_k[BSZ * SEQ * DIM];
__device__ float g_v[BSZ * SEQ * DIM];
__device__ float g_att[BSZ * SEQ * DIM];  // [b,n,h*hd]
__device__ __nv_bfloat16 g_xh[MTOT * DIM];   // split-bf16 A operand (x / att)
__device__ __nv_bfloat16 g_xl[MTOT * DIM];
__device__ __nv_bfloat16 g_wh[DIM * DIM];    // split-bf16 B operand (weights)
__device__ __nv_bfloat16 g_wl[DIM * DIM];

// ---------------------------- helpers ---------------------------------------
__device__ __forceinline__ uint32_t s2u(const void* p) {
    uint32_t a;
    asm("{ .reg .u64 t; cvta.to.shared.u64 t, %1; cvt.u32.u64 %0, t; }"
        : "=r"(a) : "l"(p));
    return a;
}

#define LDSM4(r, a)                                                            \
    asm volatile(                                                              \
        "ldmatrix.sync.aligned.m8n8.x4.shared.b16 {%0,%1,%2,%3}, [%4];"        \
        : "=r"((r)[0]), "=r"((r)[1]), "=r"((r)[2]), "=r"((r)[3]) : "r"(a))

#define MMA16816(d, a, b)                                                      \
    asm volatile(                                                              \
        "mma.sync.aligned.m16n8k16.row.col.f32.bf16.bf16.f32 "                 \
        "{%0,%1,%2,%3}, {%4,%5,%6,%7}, {%8,%9}, {%0,%1,%2,%3};"                \
        : "+f"((d)[0]), "+f"((d)[1]), "+f"((d)[2]), "+f"((d)[3])               \
        : "r"((a)[0]), "r"((a)[1]), "r"((a)[2]), "r"((a)[3]),                  \
          "r"((b)[0]), "r"((b)[1]))

// ---------------------------------------------------------------------------
// split fp32 -> (hi, lo) bf16. n/4 threads, float4 per thread.
// ---------------------------------------------------------------------------
__global__ void __launch_bounds__(256) split_kernel(
    const float* __restrict__ src, __nv_bfloat16* __restrict__ hi,
    __nv_bfloat16* __restrict__ lo)
{
    int i = blockIdx.x * blockDim.x + threadIdx.x;
    float4 v = ((const float4*)src)[i];
    __nv_bfloat16 h0 = __float2bfloat16(v.x), h1 = __float2bfloat16(v.y);
    __nv_bfloat16 h2 = __float2bfloat16(v.z), h3 = __float2bfloat16(v.w);
    __nv_bfloat16 l0 = __float2bfloat16(v.x - __bfloat162float(h0));
    __nv_bfloat16 l1 = __float2bfloat16(v.y - __bfloat162float(h1));
    __nv_bfloat16 l2 = __float2bfloat16(v.z - __bfloat162float(h2));
    __nv_bfloat16 l3 = __float2bfloat16(v.w - __bfloat162float(h3));
    ushort4 H, L;
    H.x = *(unsigned short*)&h0; H.y = *(unsigned short*)&h1;
    H.z = *(unsigned short*)&h2; H.w = *(unsigned short*)&h3;
    L.x = *(unsigned short*)&l0; L.y = *(unsigned short*)&l1;
    L.z = *(unsigned short*)&l2; L.w = *(unsigned short*)&l3;
    ((ushort4*)hi)[i] = H;
    ((ushort4*)lo)[i] = L;
}

// ---------------------------------------------------------------------------
// HMMA split-bf16 GEMM: C[m,n] = sum_k A[m,k]*B[n,k]
// M=4096, N=2048, K=2048. CTA: 128x128 tile, BK=32, 256 threads.
// Warp tile 64x32 (warp grid 2x4). 3 products per accumulate (Ah*Bh+Ah*Bl+Al*Bh).
// Smem stride 56 bf16 (112B): 16B aligned, conflict-free ldmatrix.
// Double-buffered, one __syncthreads per chunk.
// ---------------------------------------------------------------------------
#define SSTR 56
#define TILE_BYTES (128 * SSTR * 2)   // 14336
#define BUF_BYTES  (4 * TILE_BYTES)   // 57344
#define SMEM_DYN   (2 * BUF_BYTES)    // 114688

__global__ void __launch_bounds__(256) mma_gemm_kernel(
    const __nv_bfloat16* __restrict__ Ah, const __nv_bfloat16* __restrict__ Al,
    const __nv_bfloat16* __restrict__ Bh, const __nv_bfloat16* __restrict__ Bl,
    float* __restrict__ C, int headmajor)
{
    extern __shared__ __align__(16) char smem[];
    const int tid = threadIdx.x;
    const int lane = tid & 31;
    const int wid = tid >> 5;
    const int bm = blockIdx.y * 128, bn = blockIdx.x * 128;
    const int wm = (wid >> 2) * 64, wn = (wid & 3) * 32;
    const uint32_t sbase = s2u(smem);

    float acc[4][4][4];
#pragma unroll
    for (int i = 0; i < 4; i++)
#pragma unroll
        for (int j = 0; j < 4; j++)
#pragma unroll
            for (int r = 0; r < 4; r++) acc[i][j][r] = 0.f;

    // global->smem staging map: thread -> rows (sr, sr+64), 16B granule cq
    const int sr = tid >> 2;
    const int cq = tid & 3;
    const size_t gA0 = (size_t)(bm + sr) * DIM + cq * 8;
    const size_t gA1 = gA0 + (size_t)64 * DIM;
    const size_t gB0 = (size_t)(bn + sr) * DIM + cq * 8;
    const size_t gB1 = gB0 + (size_t)64 * DIM;
    const uint32_t so0 = sr * 112 + cq * 16;
    const uint32_t so1 = (sr + 64) * 112 + cq * 16;

    // ldmatrix lane address components
    // A x4 tiles: {r0-7,k0-7},{r8-15,k0-7},{r0-7,k8-15},{r8-15,k8-15}
    const int a_row = wm + (lane & 7) + ((lane >> 3) & 1) * 8;
    const int a_kc  = (lane >> 4) * 8;
    // B x4 tiles: {n0-7,k0-7},{n0-7,k8-15},{n8-15,k0-7},{n8-15,k8-15}
    const int b_row = wn + ((lane >> 4) & 1) * 8 + (lane & 7);
    const int b_kc  = ((lane >> 3) & 1) * 8;

    uint4 stg[8];
    // preload chunk 0
    stg[0] = *(const uint4*)(Ah + gA0); stg[1] = *(const uint4*)(Ah + gA1);
    stg[2] = *(const uint4*)(Al + gA0); stg[3] = *(const uint4*)(Al + gA1);
    stg[4] = *(const uint4*)(Bh + gB0); stg[5] = *(const uint4*)(Bh + gB1);
    stg[6] = *(const uint4*)(Bl + gB0); stg[7] = *(const uint4*)(Bl + gB1);

    for (int c = 0; c < 64; c++) {
        // commit staged chunk c into buffer c&1
        {
            char* p = smem + (c & 1) * BUF_BYTES;
            *(uint4*)(p + so0)                  = stg[0];
            *(uint4*)(p + so1)                  = stg[1];
            *(uint4*)(p + TILE_BYTES + so0)     = stg[2];
            *(uint4*)(p + TILE_BYTES + so1)     = stg[3];
            *(uint4*)(p + 2 * TILE_BYTES + so0) = stg[4];
            *(uint4*)(p + 2 * TILE_BYTES + so1) = stg[5];
            *(uint4*)(p + 3 * TILE_BYTES + so0) = stg[6];
            *(uint4*)(p + 3 * TILE_BYTES + so1) = stg[7];
        }
        __syncthreads();
        // issue global loads for chunk c+1 (hidden under compute)
        if (c + 1 < 64) {
            const int k0 = (c + 1) * 32;
            stg[0] = *(const uint4*)(Ah + gA0 + k0);
            stg[1] = *(const uint4*)(Ah + gA1 + k0);
            stg[2] = *(const uint4*)(Al + gA0 + k0);
            stg[3] = *(const uint4*)(Al + gA1 + k0);
            stg[4] = *(const uint4*)(Bh + gB0 + k0);
            stg[5] = *(const uint4*)(Bh + gB1 + k0);
            stg[6] = *(const uint4*)(Bl + gB0 + k0);
            stg[7] = *(const uint4*)(Bl + gB1 + k0);
        }
        // compute chunk c
        const uint32_t base = sbase + (c & 1) * BUF_BYTES;
#pragma unroll
        for (int ks = 0; ks < 2; ks++) {
            uint32_t ah[4][4], al[4][4], bh[4][2], bl[4][2];
#pragma unroll
            for (int mt = 0; mt < 4; mt++) {
                uint32_t ra = base + (uint32_t)(a_row + mt * 16) * 112
                            + (uint32_t)(ks * 16 + a_kc) * 2;
                LDSM4(ah[mt], ra);
                LDSM4(al[mt], ra + TILE_BYTES);
            }
#pragma unroll
            for (int pr = 0; pr < 2; pr++) {
                uint32_t rb = base + 2 * TILE_BYTES
                            + (uint32_t)(b_row + pr * 16) * 112
                            + (uint32_t)(ks * 16 + b_kc) * 2;
                uint32_t t[4];
                LDSM4(t, rb);
                bh[2 * pr][0] = t[0]; bh[2 * pr][1] = t[1];
                bh[2 * pr + 1][0] = t[2]; bh[2 * pr + 1][1] = t[3];
                LDSM4(t, rb + TILE_BYTES);
                bl[2 * pr][0] = t[0]; bl[2 * pr][1] = t[1];
                bl[2 * pr + 1][0] = t[2]; bl[2 * pr + 1][1] = t[3];
            }
#pragma unroll
            for (int mt = 0; mt < 4; mt++)
#pragma unroll
                for (int nt = 0; nt < 4; nt++) {
                    MMA16816(acc[mt][nt], ah[mt], bh[nt]);
                    MMA16816(acc[mt][nt], ah[mt], bl[nt]);
                    MMA16816(acc[mt][nt], al[mt], bh[nt]);
                }
        }
        __syncthreads();
    }

    // epilogue: c0,c1 -> (row, col..col+1); c2,c3 -> (row+8, same cols)
#pragma unroll
    for (int mt = 0; mt < 4; mt++) {
        const int row = bm + wm + mt * 16 + (lane >> 2);
#pragma unroll
        for (int nt = 0; nt < 4; nt++) {
            const int col = bn + wn + nt * 8 + (lane & 3) * 2;
            size_t i0, i1;
            if (headmajor) {
                const int hh = col >> 7, t = col & 127;
                const int bi0 = row >> 11, ni0 = row & (SEQ - 1);
                i0 = (((size_t)bi0 * NH + hh) * SEQ + ni0) * HDIM + t;
                const int r1 = row + 8;
                const int bi1 = r1 >> 11, ni1 = r1 & (SEQ - 1);
                i1 = (((size_t)bi1 * NH + hh) * SEQ + ni1) * HDIM + t;
            } else {
                i0 = (size_t)row * DIM + col;
                i1 = (size_t)(row + 8) * DIM + col;
            }
            float2 v0 = { acc[mt][nt][0], acc[mt][nt][1] };
            float2 v1 = { acc[mt][nt][2], acc[mt][nt][3] };
            *(float2*)(C + i0) = v0;
            *(float2*)(C + i1) = v1;
        }
    }
}

// ---------------------------------------------------------------------------
// In-place RoPE on g_q, g_k (head-major [b,h,n,hd]).
// ---------------------------------------------------------------------------
__global__ void rope_kernel()
{
    int idx = blockIdx.x * blockDim.x + threadIdx.x;  // total = BSZ*NH*SEQ*64
    int t = idx & 63;
    int ni = (idx >> 6) & (SEQ - 1);
    int bh = idx >> 17;
    size_t base = ((size_t)bh * SEQ + ni) * HDIM;

    float theta = expf((float)t * -0.14391156831f);  // ln(10000)/64
    float ang = (float)ni * theta;
    float s, c;
    sincosf(ang, &s, &c);

    float q1 = g_q[base + t], q2 = g_q[base + t + 64];
    g_q[base + t]      = q1 * c - q2 * s;
    g_q[base + t + 64] = q1 * s + q2 * c;
    float k1 = g_k[base + t], k2 = g_k[base + t + 64];
    g_k[base + t]      = k1 * c - k2 * s;
    g_k[base + t + 64] = k1 * s + k2 * c;
}

// ---------------------------------------------------------------------------
// Poly attention: per (b,h), scores = (q.k)^4 causal; out = scores@v / sum.
// ---------------------------------------------------------------------------
__global__ void __launch_bounds__(256) attn_kernel(float* __restrict__ O)
{
    __shared__ float Qts[128 * 33];
    __shared__ float Kts[128 * 33];
    __shared__ float Vs[32 * 128];
    __shared__ float Ss[32 * 33];
    __shared__ float Dsm[32];

    const int tid = threadIdx.x;
    const int q0 = blockIdx.x * 32;
    const int h = blockIdx.y;
    const int bi = blockIdx.z;
    const size_t hb = (((size_t)bi * NH + h) * SEQ) * HDIM;
    const float* Qb = g_q + hb;
    const float* Kb = g_k + hb;
    const float* Vb = g_v + hb;

    for (int i = tid; i < 32 * 32; i += 256) {
        int r = i >> 5;
        int c = (i & 31) << 2;
        float4 v = *(const float4*)(Qb + (size_t)(q0 + r) * HDIM + c);
        Qts[(c + 0) * 33 + r] = v.x;
        Qts[(c + 1) * 33 + r] = v.y;
        Qts[(c + 2) * 33 + r] = v.z;
        Qts[(c + 3) * 33 + r] = v.w;
    }

    const int ty = tid >> 4, tx = tid & 15;
    const int qi = tid & 31, dg = tid >> 5;
    const int d0 = dg << 4;

    float acc[16];
#pragma unroll
    for (int i = 0; i < 16; i++) acc[i] = 0.f;
    float denom = 0.f;

    const int nk = q0 + 32;
    for (int j0 = 0; j0 < nk; j0 += 32) {
        __syncthreads();
        for (int i = tid; i < 32 * 32; i += 256) {
            int r = i >> 5;
            int c = (i & 31) << 2;
            float4 kv = *(const float4*)(Kb + (size_t)(j0 + r) * HDIM + c);
            Kts[(c + 0) * 33 + r] = kv.x;
            Kts[(c + 1) * 33 + r] = kv.y;
            Kts[(c + 2) * 33 + r] = kv.z;
            Kts[(c + 3) * 33 + r] = kv.w;
            *(float4*)(Vs + r * HDIM + c) =
                *(const float4*)(Vb + (size_t)(j0 + r) * HDIM + c);
        }
        __syncthreads();

        float s00 = 0.f, s01 = 0.f, s10 = 0.f, s11 = 0.f;
        const int a0i = ty * 2, b0i = tx * 2;
#pragma unroll 8
        for (int t = 0; t < 128; t++) {
            float a0 = Qts[t * 33 + a0i];
            float a1 = Qts[t * 33 + a0i + 1];
            float b0 = Kts[t * 33 + b0i];
            float b1 = Kts[t * 33 + b0i + 1];
            s00 = fmaf(a0, b0, s00);
            s01 = fmaf(a0, b1, s01);
            s10 = fmaf(a1, b0, s10);
            s11 = fmaf(a1, b1, s11);
        }
        const int iq = q0 + a0i, jg = j0 + b0i;
        float p;
        p = s00 * s00; p = p * p; if (jg     > iq    ) p = 0.f; Ss[a0i * 33 + b0i]           = p;
        p = s01 * s01; p = p * p; if (jg + 1 > iq    ) p = 0.f; Ss[a0i * 33 + b0i + 1]       = p;
        p = s10 * s10; p = p * p; if (jg     > iq + 1) p = 0.f; Ss[(a0i + 1) * 33 + b0i]     = p;
        p = s11 * s11; p = p * p; if (jg + 1 > iq + 1) p = 0.f; Ss[(a0i + 1) * 33 + b0i + 1] = p;
        __syncthreads();

#pragma unroll
        for (int j = 0; j < 32; j++) {
            float s = Ss[qi * 33 + j];
            if (dg == 0) denom += s;
            float4 v0 = *(const float4*)(Vs + j * HDIM + d0);
            float4 v1 = *(const float4*)(Vs + j * HDIM + d0 + 4);
            float4 v2 = *(const float4*)(Vs + j * HDIM + d0 + 8);
            float4 v3 = *(const float4*)(Vs + j * HDIM + d0 + 12);
            acc[0]  = fmaf(s, v0.x, acc[0]);  acc[1]  = fmaf(s, v0.y, acc[1]);
            acc[2]  = fmaf(s, v0.z, acc[2]);  acc[3]  = fmaf(s, v0.w, acc[3]);
            acc[4]  = fmaf(s, v1.x, acc[4]);  acc[5]  = fmaf(s, v1.y, acc[5]);
            acc[6]  = fmaf(s, v1.z, acc[6]);  acc[7]  = fmaf(s, v1.w, acc[7]);
            acc[8]  = fmaf(s, v2.x, acc[8]);  acc[9]  = fmaf(s, v2.y, acc[9]);
            acc[10] = fmaf(s, v2.z, acc[10]); acc[11] = fmaf(s, v2.w, acc[11]);
            acc[12] = fmaf(s, v3.x, acc[12]); acc[13] = fmaf(s, v3.y, acc[13]);
            acc[14] = fmaf(s, v3.z, acc[14]); acc[15] = fmaf(s, v3.w, acc[15]);
        }
    }

    if (dg == 0) Dsm[qi] = denom;
    __syncthreads();
    float inv = 1.f / fmaxf(Dsm[qi], 1e-6f);

    float* Op = O + ((size_t)bi * SEQ + q0 + qi) * DIM + h * HDIM + d0;
#pragma unroll
    for (int i = 0; i < 16; i++) Op[i] = acc[i] * inv;
}

// ---------------------------------------------------------------------------
extern "C" void kernel_launch(void* const* d_in, const int* in_sizes, int n_in,
                              void* d_out, int out_size)
{
    const float* x  = (const float*)d_in[0];
    const float* Wq = (const float*)d_in[1];
    const float* Wk = (const float*)d_in[2];
    const float* Wv = (const float*)d_in[3];
    const float* Wo = (const float*)d_in[4];
    float* out = (float*)d_out;

    float *q, *k, *v, *att;
    __nv_bfloat16 *xh, *xl, *wh, *wl;
    cudaGetSymbolAddress((void**)&q, g_q);
    cudaGetSymbolAddress((void**)&k, g_k);
    cudaGetSymbolAddress((void**)&v, g_v);
    cudaGetSymbolAddress((void**)&att, g_att);
    cudaGetSymbolAddress((void**)&xh, g_xh);
    cudaGetSymbolAddress((void**)&xl, g_xl);
    cudaGetSymbolAddress((void**)&wh, g_wh);
    cudaGetSymbolAddress((void**)&wl, g_wl);

    cudaFuncSetAttribute(mma_gemm_kernel,
                         cudaFuncAttributeMaxDynamicSharedMemorySize, SMEM_DYN);

    const int xblocks = (MTOT * DIM / 4) / 256;   // 8192
    const int wblocks = (DIM * DIM / 4) / 256;    // 4096
    dim3 ggrid(DIM / 128, MTOT / 128);            // (16, 32)

    split_kernel<<<xblocks, 256>>>(x, xh, xl);

    split_kernel<<<wblocks, 256>>>(Wq, wh, wl);
    mma_gemm_kernel<<<ggrid, 256, SMEM_DYN>>>(xh, xl, wh, wl, q, 1);

    split_kernel<<<wblocks, 256>>>(Wk, wh, wl);
    mma_gemm_kernel<<<ggrid, 256, SMEM_DYN>>>(xh, xl, wh, wl, k, 1);

    split_kernel<<<wblocks, 256>>>(Wv, wh, wl);
    mma_gemm_kernel<<<ggrid, 256, SMEM_DYN>>>(xh, xl, wh, wl, v, 1);

    rope_kernel<<<(BSZ * NH * SEQ * 64) / 256, 256>>>();

    attn_kernel<<<dim3(SEQ / 32, NH, BSZ), 256>>>(att);

    split_kernel<<<xblocks, 256>>>(att, xh, xl);
    split_kernel<<<wblocks, 256>>>(Wo, wh, wl);
    mma_gemm_kernel<<<ggrid, 256, SMEM_DYN>>>(xh, xl, wh, wl, out, 0);
}

// round 6
// speedup vs baseline: 3.2201x; 1.7824x over previous
#include <cuda_runtime.h>
#include <cuda_bf16.h>
#include <math.h>
#include <stdint.h>

#define BSZ 2
#define SEQ 2048
#define DIM 2048
#define NH 16
#define HDIM 128
#define MTOT (BSZ * SEQ)   // 4096

// ---------------- scratch (device globals; no allocs allowed) ---------------
__device__ float g_q[BSZ * SEQ * DIM];    // [b,h,n,hd] fp32 (pre-rope)
__device__ float g_k[BSZ * SEQ * DIM];
__device__ float g_v[BSZ * SEQ * DIM];
__device__ float g_att[BSZ * SEQ * DIM];  // [b,n,h*hd]
__device__ __nv_bfloat16 g_xh[MTOT * DIM];   // split-bf16 A operand (x / att)
__device__ __nv_bfloat16 g_xl[MTOT * DIM];
__device__ __nv_bfloat16 g_wh[DIM * DIM];    // split-bf16 B operand (weights)
__device__ __nv_bfloat16 g_wl[DIM * DIM];
// attention split operands [b,h,n,hd] bf16
__device__ __nv_bfloat16 g_qh[BSZ * SEQ * DIM];
__device__ __nv_bfloat16 g_ql[BSZ * SEQ * DIM];
__device__ __nv_bfloat16 g_kh[BSZ * SEQ * DIM];
__device__ __nv_bfloat16 g_kl[BSZ * SEQ * DIM];
__device__ __nv_bfloat16 g_vh[BSZ * SEQ * DIM];
__device__ __nv_bfloat16 g_vl[BSZ * SEQ * DIM];

// ---------------------------- helpers ---------------------------------------
__device__ __forceinline__ uint32_t s2u(const void* p) {
    uint32_t a;
    asm("{ .reg .u64 t; cvta.to.shared.u64 t, %1; cvt.u32.u64 %0, t; }"
        : "=r"(a) : "l"(p));
    return a;
}

#define LDSM4(r, a)                                                            \
    asm volatile(                                                              \
        "ldmatrix.sync.aligned.m8n8.x4.shared.b16 {%0,%1,%2,%3}, [%4];"        \
        : "=r"((r)[0]), "=r"((r)[1]), "=r"((r)[2]), "=r"((r)[3]) : "r"(a))

#define LDSM4T(r, a)                                                           \
    asm volatile(                                                              \
        "ldmatrix.sync.aligned.m8n8.x4.trans.shared.b16 {%0,%1,%2,%3}, [%4];"  \
        : "=r"((r)[0]), "=r"((r)[1]), "=r"((r)[2]), "=r"((r)[3]) : "r"(a))

#define MMA16816(d, a, b)                                                      \
    asm volatile(                                                              \
        "mma.sync.aligned.m16n8k16.row.col.f32.bf16.bf16.f32 "                 \
        "{%0,%1,%2,%3}, {%4,%5,%6,%7}, {%8,%9}, {%0,%1,%2,%3};"                \
        : "+f"((d)[0]), "+f"((d)[1]), "+f"((d)[2]), "+f"((d)[3])               \
        : "r"((a)[0]), "r"((a)[1]), "r"((a)[2]), "r"((a)[3]),                  \
          "r"((b)[0]), "r"((b)[1]))

__device__ __forceinline__ uint32_t packbf(float lo, float hi) {
    __nv_bfloat162 t = __floats2bfloat162_rn(lo, hi);  // .x = lo, .y = hi
    return *(uint32_t*)&t;
}

// ---------------------------------------------------------------------------
// split fp32 -> (hi, lo) bf16. n/4 threads, float4 per thread.
// ---------------------------------------------------------------------------
__global__ void __launch_bounds__(256) split_kernel(
    const float* __restrict__ src, __nv_bfloat16* __restrict__ hi,
    __nv_bfloat16* __restrict__ lo)
{
    int i = blockIdx.x * blockDim.x + threadIdx.x;
    float4 v = ((const float4*)src)[i];
    __nv_bfloat16 h0 = __float2bfloat16(v.x), h1 = __float2bfloat16(v.y);
    __nv_bfloat16 h2 = __float2bfloat16(v.z), h3 = __float2bfloat16(v.w);
    __nv_bfloat16 l0 = __float2bfloat16(v.x - __bfloat162float(h0));
    __nv_bfloat16 l1 = __float2bfloat16(v.y - __bfloat162float(h1));
    __nv_bfloat16 l2 = __float2bfloat16(v.z - __bfloat162float(h2));
    __nv_bfloat16 l3 = __float2bfloat16(v.w - __bfloat162float(h3));
    ushort4 H, L;
    H.x = *(unsigned short*)&h0; H.y = *(unsigned short*)&h1;
    H.z = *(unsigned short*)&h2; H.w = *(unsigned short*)&h3;
    L.x = *(unsigned short*)&l0; L.y = *(unsigned short*)&l1;
    L.z = *(unsigned short*)&l2; L.w = *(unsigned short*)&l3;
    ((ushort4*)hi)[i] = H;
    ((ushort4*)lo)[i] = L;
}

// ---------------------------------------------------------------------------
// HMMA split-bf16 GEMM (unchanged from round 5, validated).
// ---------------------------------------------------------------------------
#define SSTR 56
#define TILE_BYTES (128 * SSTR * 2)   // 14336
#define BUF_BYTES  (4 * TILE_BYTES)   // 57344
#define SMEM_DYN   (2 * BUF_BYTES)    // 114688

__global__ void __launch_bounds__(256) mma_gemm_kernel(
    const __nv_bfloat16* __restrict__ Ah, const __nv_bfloat16* __restrict__ Al,
    const __nv_bfloat16* __restrict__ Bh, const __nv_bfloat16* __restrict__ Bl,
    float* __restrict__ C, int headmajor)
{
    extern __shared__ __align__(16) char smem[];
    const int tid = threadIdx.x;
    const int lane = tid & 31;
    const int wid = tid >> 5;
    const int bm = blockIdx.y * 128, bn = blockIdx.x * 128;
    const int wm = (wid >> 2) * 64, wn = (wid & 3) * 32;
    const uint32_t sbase = s2u(smem);

    float acc[4][4][4];
#pragma unroll
    for (int i = 0; i < 4; i++)
#pragma unroll
        for (int j = 0; j < 4; j++)
#pragma unroll
            for (int r = 0; r < 4; r++) acc[i][j][r] = 0.f;

    const int sr = tid >> 2;
    const int cq = tid & 3;
    const size_t gA0 = (size_t)(bm + sr) * DIM + cq * 8;
    const size_t gA1 = gA0 + (size_t)64 * DIM;
    const size_t gB0 = (size_t)(bn + sr) * DIM + cq * 8;
    const size_t gB1 = gB0 + (size_t)64 * DIM;
    const uint32_t so0 = sr * 112 + cq * 16;
    const uint32_t so1 = (sr + 64) * 112 + cq * 16;

    const int a_row = wm + (lane & 7) + ((lane >> 3) & 1) * 8;
    const int a_kc  = (lane >> 4) * 8;
    const int b_row = wn + ((lane >> 4) & 1) * 8 + (lane & 7);
    const int b_kc  = ((lane >> 3) & 1) * 8;

    uint4 stg[8];
    stg[0] = *(const uint4*)(Ah + gA0); stg[1] = *(const uint4*)(Ah + gA1);
    stg[2] = *(const uint4*)(Al + gA0); stg[3] = *(const uint4*)(Al + gA1);
    stg[4] = *(const uint4*)(Bh + gB0); stg[5] = *(const uint4*)(Bh + gB1);
    stg[6] = *(const uint4*)(Bl + gB0); stg[7] = *(const uint4*)(Bl + gB1);

    for (int c = 0; c < 64; c++) {
        {
            char* p = smem + (c & 1) * BUF_BYTES;
            *(uint4*)(p + so0)                  = stg[0];
            *(uint4*)(p + so1)                  = stg[1];
            *(uint4*)(p + TILE_BYTES + so0)     = stg[2];
            *(uint4*)(p + TILE_BYTES + so1)     = stg[3];
            *(uint4*)(p + 2 * TILE_BYTES + so0) = stg[4];
            *(uint4*)(p + 2 * TILE_BYTES + so1) = stg[5];
            *(uint4*)(p + 3 * TILE_BYTES + so0) = stg[6];
            *(uint4*)(p + 3 * TILE_BYTES + so1) = stg[7];
        }
        __syncthreads();
        if (c + 1 < 64) {
            const int k0 = (c + 1) * 32;
            stg[0] = *(const uint4*)(Ah + gA0 + k0);
            stg[1] = *(const uint4*)(Ah + gA1 + k0);
            stg[2] = *(const uint4*)(Al + gA0 + k0);
            stg[3] = *(const uint4*)(Al + gA1 + k0);
            stg[4] = *(const uint4*)(Bh + gB0 + k0);
            stg[5] = *(const uint4*)(Bh + gB1 + k0);
            stg[6] = *(const uint4*)(Bl + gB0 + k0);
            stg[7] = *(const uint4*)(Bl + gB1 + k0);
        }
        const uint32_t base = sbase + (c & 1) * BUF_BYTES;
#pragma unroll
        for (int ks = 0; ks < 2; ks++) {
            uint32_t ah[4][4], al[4][4], bh[4][2], bl[4][2];
#pragma unroll
            for (int mt = 0; mt < 4; mt++) {
                uint32_t ra = base + (uint32_t)(a_row + mt * 16) * 112
                            + (uint32_t)(ks * 16 + a_kc) * 2;
                LDSM4(ah[mt], ra);
                LDSM4(al[mt], ra + TILE_BYTES);
            }
#pragma unroll
            for (int pr = 0; pr < 2; pr++) {
                uint32_t rb = base + 2 * TILE_BYTES
                            + (uint32_t)(b_row + pr * 16) * 112
                            + (uint32_t)(ks * 16 + b_kc) * 2;
                uint32_t t[4];
                LDSM4(t, rb);
                bh[2 * pr][0] = t[0]; bh[2 * pr][1] = t[1];
                bh[2 * pr + 1][0] = t[2]; bh[2 * pr + 1][1] = t[3];
                LDSM4(t, rb + TILE_BYTES);
                bl[2 * pr][0] = t[0]; bl[2 * pr][1] = t[1];
                bl[2 * pr + 1][0] = t[2]; bl[2 * pr + 1][1] = t[3];
            }
#pragma unroll
            for (int mt = 0; mt < 4; mt++)
#pragma unroll
                for (int nt = 0; nt < 4; nt++) {
                    MMA16816(acc[mt][nt], ah[mt], bh[nt]);
                    MMA16816(acc[mt][nt], ah[mt], bl[nt]);
                    MMA16816(acc[mt][nt], al[mt], bh[nt]);
                }
        }
        __syncthreads();
    }

#pragma unroll
    for (int mt = 0; mt < 4; mt++) {
        const int row = bm + wm + mt * 16 + (lane >> 2);
#pragma unroll
        for (int nt = 0; nt < 4; nt++) {
            const int col = bn + wn + nt * 8 + (lane & 3) * 2;
            size_t i0, i1;
            if (headmajor) {
                const int hh = col >> 7, t = col & 127;
                const int bi0 = row >> 11, ni0 = row & (SEQ - 1);
                i0 = (((size_t)bi0 * NH + hh) * SEQ + ni0) * HDIM + t;
                const int r1 = row + 8;
                const int bi1 = r1 >> 11, ni1 = r1 & (SEQ - 1);
                i1 = (((size_t)bi1 * NH + hh) * SEQ + ni1) * HDIM + t;
            } else {
                i0 = (size_t)row * DIM + col;
                i1 = (size_t)(row + 8) * DIM + col;
            }
            float2 v0 = { acc[mt][nt][0], acc[mt][nt][1] };
            float2 v1 = { acc[mt][nt][2], acc[mt][nt][3] };
            *(float2*)(C + i0) = v0;
            *(float2*)(C + i1) = v1;
        }
    }
}

// ---------------------------------------------------------------------------
// RoPE + bf16 hi/lo split: g_q/g_k fp32 -> g_qh/ql/kh/kl.
// ---------------------------------------------------------------------------
__global__ void rope_split_kernel()
{
    int idx = blockIdx.x * blockDim.x + threadIdx.x;  // BSZ*NH*SEQ*64
    int t = idx & 63;
    int ni = (idx >> 6) & (SEQ - 1);
    int bh = idx >> 17;
    size_t base = ((size_t)bh * SEQ + ni) * HDIM;

    float theta = expf((float)t * -0.14391156831f);  // ln(10000)/64
    float ang = (float)ni * theta;
    float s, c;
    sincosf(ang, &s, &c);

    float q1 = g_q[base + t], q2 = g_q[base + t + 64];
    float k1 = g_k[base + t], k2 = g_k[base + t + 64];
    float qa = q1 * c - q2 * s, qb = q1 * s + q2 * c;
    float ka = k1 * c - k2 * s, kb = k1 * s + k2 * c;

    __nv_bfloat16 h;
    h = __float2bfloat16(qa); g_qh[base + t] = h;
    g_ql[base + t] = __float2bfloat16(qa - __bfloat162float(h));
    h = __float2bfloat16(qb); g_qh[base + t + 64] = h;
    g_ql[base + t + 64] = __float2bfloat16(qb - __bfloat162float(h));
    h = __float2bfloat16(ka); g_kh[base + t] = h;
    g_kl[base + t] = __float2bfloat16(ka - __bfloat162float(h));
    h = __float2bfloat16(kb); g_kh[base + t + 64] = h;
    g_kl[base + t + 64] = __float2bfloat16(kb - __bfloat162float(h));
}

// ---------------------------------------------------------------------------
// Tensor-core poly attention.
// CTA = 64 queries x (64-key tiles), 4 warps (16 q-rows each), 128 threads.
// QK^T: split-bf16 3-product HMMA; s^4+mask+denom in registers; accumulator
// fragments repacked directly into A fragments (hi/lo) for S@V (3-product).
// smem per CTA: Qh,Ql,Kh,Kl,Vh,Vl tiles 64x128 bf16, row stride 272B.
// ---------------------------------------------------------------------------
#define ASTR 272
#define OQH 0
#define OQL 17408
#define OKH 34816
#define OKL 52224
#define OVH 69632
#define OVL 87040
#define ATT_SMEM 104448

__global__ void __launch_bounds__(128) attn_tc_kernel()
{
    extern __shared__ __align__(16) char sm[];
    const int tid = threadIdx.x, lane = tid & 31, wid = tid >> 5;
    const int q0 = blockIdx.x * 64;
    const int h = blockIdx.y, bi = blockIdx.z;
    const size_t bh = ((size_t)bi * NH + h) * SEQ;
    const uint32_t sb = s2u(sm);
    const int wq = wid * 16;
    const int g = lane >> 2, tig = lane & 3;
    const uint32_t lrow = lane & 15;
    const uint32_t lseg = (lane >> 4) * 16;

    // stage Q tile (rows q0..q0+63)
    for (int i = tid; i < 64 * 16; i += 128) {
        int r = i >> 4, gg = i & 15;
        size_t ga = (bh + q0 + r) * HDIM + gg * 8;
        *(uint4*)(sm + OQH + r * ASTR + gg * 16) = *(const uint4*)(g_qh + ga);
        *(uint4*)(sm + OQL + r * ASTR + gg * 16) = *(const uint4*)(g_ql + ga);
    }

    float acc[16][4];
#pragma unroll
    for (int i = 0; i < 16; i++)
#pragma unroll
        for (int r = 0; r < 4; r++) acc[i][r] = 0.f;
    float dr = 0.f, dr8 = 0.f;

    const uint32_t qa_base = sb + OQH + (uint32_t)(wq + lrow) * ASTR + lseg;
    const int qg = q0 + wq + g, qg8 = qg + 8;

    for (int j0 = 0; j0 <= q0; j0 += 64) {
        __syncthreads();
        for (int i = tid; i < 64 * 16; i += 128) {
            int r = i >> 4, gg = i & 15;
            size_t ga = (bh + j0 + r) * HDIM + gg * 8;
            uint32_t so = r * ASTR + gg * 16;
            *(uint4*)(sm + OKH + so) = *(const uint4*)(g_kh + ga);
            *(uint4*)(sm + OKL + so) = *(const uint4*)(g_kl + ga);
            *(uint4*)(sm + OVH + so) = *(const uint4*)(g_vh + ga);
            *(uint4*)(sm + OVL + so) = *(const uint4*)(g_vl + ga);
        }
        __syncthreads();

        // ---- QK^T: scores c[8][4] over 64 keys ----
        float c[8][4];
#pragma unroll
        for (int nt = 0; nt < 8; nt++)
#pragma unroll
            for (int r = 0; r < 4; r++) c[nt][r] = 0.f;

#pragma unroll
        for (int kc = 0; kc < 8; kc++) {
            uint32_t ah4[4], al4[4];
            LDSM4(ah4, qa_base + kc * 32);
            LDSM4(al4, qa_base + (OQL - OQH) + kc * 32);
#pragma unroll
            for (int j2 = 0; j2 < 4; j2++) {
                uint32_t rb = sb + OKH + (uint32_t)(j2 * 16 + lrow) * ASTR
                            + kc * 32 + lseg;
                uint32_t kh4[4], kl4[4];
                LDSM4(kh4, rb);
                LDSM4(kl4, rb + (OKL - OKH));
                uint32_t b0h[2] = { kh4[0], kh4[2] }, b1h[2] = { kh4[1], kh4[3] };
                uint32_t b0l[2] = { kl4[0], kl4[2] }, b1l[2] = { kl4[1], kl4[3] };
                MMA16816(c[2 * j2],     ah4, b0h);
                MMA16816(c[2 * j2],     ah4, b0l);
                MMA16816(c[2 * j2],     al4, b0h);
                MMA16816(c[2 * j2 + 1], ah4, b1h);
                MMA16816(c[2 * j2 + 1], ah4, b1l);
                MMA16816(c[2 * j2 + 1], al4, b1h);
            }
        }

        // ---- s^4, causal mask, denom, repack to bf16 hi/lo A-fragments ----
        uint32_t sh[4][4], sl[4][4];
        const bool diag = (j0 == q0);
#pragma unroll
        for (int nt = 0; nt < 8; nt++) {
            const int kcol = j0 + nt * 8 + 2 * tig;
            float t2, p0, p1, p2, p3;
            t2 = c[nt][0] * c[nt][0]; p0 = t2 * t2;
            t2 = c[nt][1] * c[nt][1]; p1 = t2 * t2;
            t2 = c[nt][2] * c[nt][2]; p2 = t2 * t2;
            t2 = c[nt][3] * c[nt][3]; p3 = t2 * t2;
            if (diag) {
                if (kcol     > qg)  p0 = 0.f;
                if (kcol + 1 > qg)  p1 = 0.f;
                if (kcol     > qg8) p2 = 0.f;
                if (kcol + 1 > qg8) p3 = 0.f;
            }
            dr  += p0 + p1;
            dr8 += p2 + p3;
            const int kf = nt >> 1, hi2 = (nt & 1) * 2;
            uint32_t ph01 = packbf(p0, p1);
            uint32_t ph23 = packbf(p2, p3);
            __nv_bfloat162 hv01 = *(__nv_bfloat162*)&ph01;
            __nv_bfloat162 hv23 = *(__nv_bfloat162*)&ph23;
            sh[kf][hi2]     = ph01;
            sh[kf][hi2 + 1] = ph23;
            sl[kf][hi2]     = packbf(p0 - __bfloat162float(hv01.x),
                                     p1 - __bfloat162float(hv01.y));
            sl[kf][hi2 + 1] = packbf(p2 - __bfloat162float(hv23.x),
                                     p3 - __bfloat162float(hv23.y));
        }

        // ---- S @ V ----
#pragma unroll
        for (int d2 = 0; d2 < 8; d2++) {
#pragma unroll
            for (int kf = 0; kf < 4; kf++) {
                uint32_t rv = sb + OVH + (uint32_t)(kf * 16 + lrow) * ASTR
                            + d2 * 32 + lseg;
                uint32_t vh4[4], vl4[4];
                LDSM4T(vh4, rv);
                LDSM4T(vl4, rv + (OVL - OVH));
                uint32_t bv0h[2] = { vh4[0], vh4[1] }, bv1h[2] = { vh4[2], vh4[3] };
                uint32_t bv0l[2] = { vl4[0], vl4[1] }, bv1l[2] = { vl4[2], vl4[3] };
                MMA16816(acc[2 * d2],     sh[kf], bv0h);
                MMA16816(acc[2 * d2],     sh[kf], bv0l);
                MMA16816(acc[2 * d2],     sl[kf], bv0h);
                MMA16816(acc[2 * d2 + 1], sh[kf], bv1h);
                MMA16816(acc[2 * d2 + 1], sh[kf], bv1l);
                MMA16816(acc[2 * d2 + 1], sl[kf], bv1h);
            }
        }
    }

    // denom reduce across the 4 lanes of each row-quad
    dr  += __shfl_xor_sync(0xFFFFFFFFu, dr, 1);
    dr  += __shfl_xor_sync(0xFFFFFFFFu, dr, 2);
    dr8 += __shfl_xor_sync(0xFFFFFFFFu, dr8, 1);
    dr8 += __shfl_xor_sync(0xFFFFFFFFu, dr8, 2);
    const float inv  = 1.f / fmaxf(dr, 1e-6f);
    const float inv8 = 1.f / fmaxf(dr8, 1e-6f);

    // write [b, n, h*128]
    const int n0 = q0 + wq + g;
#pragma unroll
    for (int dg = 0; dg < 16; dg++) {
        const int col = h * HDIM + dg * 8 + 2 * tig;
        float2 v0 = { acc[dg][0] * inv,  acc[dg][1] * inv  };
        float2 v1 = { acc[dg][2] * inv8, acc[dg][3] * inv8 };
        *(float2*)(g_att + ((size_t)bi * SEQ + n0) * DIM + col) = v0;
        *(float2*)(g_att + ((size_t)bi * SEQ + n0 + 8) * DIM + col) = v1;
    }
}

// ---------------------------------------------------------------------------
extern "C" void kernel_launch(void* const* d_in, const int* in_sizes, int n_in,
                              void* d_out, int out_size)
{
    const float* x  = (const float*)d_in[0];
    const float* Wq = (const float*)d_in[1];
    const float* Wk = (const float*)d_in[2];
    const float* Wv = (const float*)d_in[3];
    const float* Wo = (const float*)d_in[4];
    float* out = (float*)d_out;

    float *q, *k, *v, *att;
    __nv_bfloat16 *xh, *xl, *wh, *wl, *vh, *vl;
    cudaGetSymbolAddress((void**)&q, g_q);
    cudaGetSymbolAddress((void**)&k, g_k);
    cudaGetSymbolAddress((void**)&v, g_v);
    cudaGetSymbolAddress((void**)&att, g_att);
    cudaGetSymbolAddress((void**)&xh, g_xh);
    cudaGetSymbolAddress((void**)&xl, g_xl);
    cudaGetSymbolAddress((void**)&wh, g_wh);
    cudaGetSymbolAddress((void**)&wl, g_wl);
    cudaGetSymbolAddress((void**)&vh, g_vh);
    cudaGetSymbolAddress((void**)&vl, g_vl);

    cudaFuncSetAttribute(mma_gemm_kernel,
                         cudaFuncAttributeMaxDynamicSharedMemorySize, SMEM_DYN);
    cudaFuncSetAttribute(attn_tc_kernel,
                         cudaFuncAttributeMaxDynamicSharedMemorySize, ATT_SMEM);

    const int xblocks = (MTOT * DIM / 4) / 256;   // 8192
    const int wblocks = (DIM * DIM / 4) / 256;    // 4096
    dim3 ggrid(DIM / 128, MTOT / 128);            // (16, 32)

    split_kernel<<<xblocks, 256>>>(x, xh, xl);

    split_kernel<<<wblocks, 256>>>(Wq, wh, wl);
    mma_gemm_kernel<<<ggrid, 256, SMEM_DYN>>>(xh, xl, wh, wl, q, 1);

    split_kernel<<<wblocks, 256>>>(Wk, wh, wl);
    mma_gemm_kernel<<<ggrid, 256, SMEM_DYN>>>(xh, xl, wh, wl, k, 1);

    split_kernel<<<wblocks, 256>>>(Wv, wh, wl);
    mma_gemm_kernel<<<ggrid, 256, SMEM_DYN>>>(xh, xl, wh, wl, v, 1);

    rope_split_kernel<<<(BSZ * NH * SEQ * 64) / 256, 256>>>();
    split_kernel<<<xblocks, 256>>>(v, vh, vl);

    attn_tc_kernel<<<dim3(SEQ / 64, NH, BSZ), 128, ATT_SMEM>>>();

    split_kernel<<<xblocks, 256>>>(att, xh, xl);
    split_kernel<<<wblocks, 256>>>(Wo, wh, wl);
    mma_gemm_kernel<<<ggrid, 256, SMEM_DYN>>>(xh, xl, wh, wl, out, 0);
}

// round 7
// speedup vs baseline: 3.2789x; 1.0183x over previous
#include <cuda_runtime.h>
#include <cuda_bf16.h>
#include <math.h>
#include <stdint.h>

#define BSZ 2
#define SEQ 2048
#define DIM 2048
#define NH 16
#define HDIM 128
#define MTOT (BSZ * SEQ)   // 4096
#define GK DIM             // K of every GEMM

// ---------------- scratch (device globals; no allocs allowed) ---------------
__device__ float g_q[BSZ * SEQ * DIM];    // [b,h,n,hd] fp32 (pre-rope)
__device__ float g_k[BSZ * SEQ * DIM];
__device__ float g_att[BSZ * SEQ * DIM];  // [b,n,h*hd]
__device__ __nv_bfloat16 g_xh[MTOT * DIM];      // split A operand (x / att)
__device__ __nv_bfloat16 g_xl[MTOT * DIM];
__device__ __nv_bfloat16 g_wh[3 * DIM * DIM];   // split B operand (Wq|Wk|Wv or Wo)
__device__ __nv_bfloat16 g_wl[3 * DIM * DIM];
// attention split operands [b,h,n,hd] bf16
__device__ __nv_bfloat16 g_qh[BSZ * SEQ * DIM];
__device__ __nv_bfloat16 g_ql[BSZ * SEQ * DIM];
__device__ __nv_bfloat16 g_kh[BSZ * SEQ * DIM];
__device__ __nv_bfloat16 g_kl[BSZ * SEQ * DIM];
__device__ __nv_bfloat16 g_vh[BSZ * SEQ * DIM];
__device__ __nv_bfloat16 g_vl[BSZ * SEQ * DIM];

// ---------------------------- helpers ---------------------------------------
__device__ __forceinline__ uint32_t s2u(const void* p) {
    uint32_t a;
    asm("{ .reg .u64 t; cvta.to.shared.u64 t, %1; cvt.u32.u64 %0, t; }"
        : "=r"(a) : "l"(p));
    return a;
}
__device__ __forceinline__ void cpa16(uint32_t s, const void* g) {
    asm volatile("cp.async.cg.shared.global [%0], [%1], 16;"
                 :: "r"(s), "l"(g));
}
#define CP_COMMIT() asm volatile("cp.async.commit_group;" ::: "memory")
#define CP_WAIT1()  asm volatile("cp.async.wait_group 1;" ::: "memory")

#define LDSM4(r, a)                                                            \
    asm volatile(                                                              \
        "ldmatrix.sync.aligned.m8n8.x4.shared.b16 {%0,%1,%2,%3}, [%4];"        \
        : "=r"((r)[0]), "=r"((r)[1]), "=r"((r)[2]), "=r"((r)[3]) : "r"(a))

#define LDSM4T(r, a)                                                           \
    asm volatile(                                                              \
        "ldmatrix.sync.aligned.m8n8.x4.trans.shared.b16 {%0,%1,%2,%3}, [%4];"  \
        : "=r"((r)[0]), "=r"((r)[1]), "=r"((r)[2]), "=r"((r)[3]) : "r"(a))

#define MMA16816(d, a, b)                                                      \
    asm volatile(                                                              \
        "mma.sync.aligned.m16n8k16.row.col.f32.bf16.bf16.f32 "                 \
        "{%0,%1,%2,%3}, {%4,%5,%6,%7}, {%8,%9}, {%0,%1,%2,%3};"                \
        : "+f"((d)[0]), "+f"((d)[1]), "+f"((d)[2]), "+f"((d)[3])               \
        : "r"((a)[0]), "r"((a)[1]), "r"((a)[2]), "r"((a)[3]),                  \
          "r"((b)[0]), "r"((b)[1]))

__device__ __forceinline__ uint32_t packbf(float lo, float hi) {
    __nv_bfloat162 t = __floats2bfloat162_rn(lo, hi);
    return *(uint32_t*)&t;
}

// ---------------------------------------------------------------------------
// split fp32 -> (hi, lo) bf16. n/4 threads, float4 per thread.
// ---------------------------------------------------------------------------
__global__ void __launch_bounds__(256) split_kernel(
    const float* __restrict__ src, __nv_bfloat16* __restrict__ hi,
    __nv_bfloat16* __restrict__ lo)
{
    int i = blockIdx.x * blockDim.x + threadIdx.x;
    float4 v = ((const float4*)src)[i];
    __nv_bfloat16 h0 = __float2bfloat16(v.x), h1 = __float2bfloat16(v.y);
    __nv_bfloat16 h2 = __float2bfloat16(v.z), h3 = __float2bfloat16(v.w);
    __nv_bfloat16 l0 = __float2bfloat16(v.x - __bfloat162float(h0));
    __nv_bfloat16 l1 = __float2bfloat16(v.y - __bfloat162float(h1));
    __nv_bfloat16 l2 = __float2bfloat16(v.z - __bfloat162float(h2));
    __nv_bfloat16 l3 = __float2bfloat16(v.w - __bfloat162float(h3));
    ushort4 H, L;
    H.x = *(unsigned short*)&h0; H.y = *(unsigned short*)&h1;
    H.z = *(unsigned short*)&h2; H.w = *(unsigned short*)&h3;
    L.x = *(unsigned short*)&l0; L.y = *(unsigned short*)&l1;
    L.z = *(unsigned short*)&l2; L.w = *(unsigned short*)&l3;
    ((ushort4*)hi)[i] = H;
    ((ushort4*)lo)[i] = L;
}

// ---------------------------------------------------------------------------
// HMMA split-bf16 GEMM with cp.async 3-stage pipeline.
// C[m,n] = sum_k A[m,k]*B[n,k].  CTA 128x128, BK=32, 256 threads, 8 warps.
// mode 0: write C[m,n] (fp32).
// mode 1: fused QKV (N=6144): cols [0,2048)->g_q, [2048,4096)->g_k head-major
//         fp32; [4096,6144)-> bf16 hi/lo split direct to g_vh/g_vl.
// ---------------------------------------------------------------------------
#define SSTR 56
#define TILE_BYTES (128 * SSTR * 2)   // 14336
#define BUF_BYTES  (4 * TILE_BYTES)   // 57344
#define SMEM_DYN   (3 * BUF_BYTES)    // 172032

__global__ void __launch_bounds__(256) mma_gemm_kernel(
    const __nv_bfloat16* __restrict__ Ah, const __nv_bfloat16* __restrict__ Al,
    const __nv_bfloat16* __restrict__ Bh, const __nv_bfloat16* __restrict__ Bl,
    float* __restrict__ C, int mode)
{
    extern __shared__ __align__(16) char smem[];
    const int tid = threadIdx.x;
    const int lane = tid & 31;
    const int wid = tid >> 5;
    const int bm = blockIdx.y * 128, bn = blockIdx.x * 128;
    const int wm = (wid >> 2) * 64, wn = (wid & 3) * 32;
    const uint32_t sbase = s2u(smem);

    float acc[4][4][4];
#pragma unroll
    for (int i = 0; i < 4; i++)
#pragma unroll
        for (int j = 0; j < 4; j++)
#pragma unroll
            for (int r = 0; r < 4; r++) acc[i][j][r] = 0.f;

    const int sr = tid >> 2;
    const int cq = tid & 3;
    const size_t gA0 = (size_t)(bm + sr) * GK + cq * 8;
    const size_t gA1 = gA0 + (size_t)64 * GK;
    const size_t gB0 = (size_t)(bn + sr) * GK + cq * 8;
    const size_t gB1 = gB0 + (size_t)64 * GK;
    const uint32_t so0 = sr * 112 + cq * 16;
    const uint32_t so1 = (sr + 64) * 112 + cq * 16;

    const int a_row = wm + (lane & 7) + ((lane >> 3) & 1) * 8;
    const int a_kc  = (lane >> 4) * 8;
    const int b_row = wn + ((lane >> 4) & 1) * 8 + (lane & 7);
    const int b_kc  = ((lane >> 3) & 1) * 8;

    // issue chunk c into stage s
    auto issue = [&](int c, int s) {
        const uint32_t sb_s = sbase + (uint32_t)s * BUF_BYTES;
        const int k0 = c * 32;
        cpa16(sb_s + so0,                  Ah + gA0 + k0);
        cpa16(sb_s + so1,                  Ah + gA1 + k0);
        cpa16(sb_s + TILE_BYTES + so0,     Al + gA0 + k0);
        cpa16(sb_s + TILE_BYTES + so1,     Al + gA1 + k0);
        cpa16(sb_s + 2 * TILE_BYTES + so0, Bh + gB0 + k0);
        cpa16(sb_s + 2 * TILE_BYTES + so1, Bh + gB1 + k0);
        cpa16(sb_s + 3 * TILE_BYTES + so0, Bl + gB0 + k0);
        cpa16(sb_s + 3 * TILE_BYTES + so1, Bl + gB1 + k0);
    };

    issue(0, 0); CP_COMMIT();
    issue(1, 1); CP_COMMIT();

    int s_cur = 0, s_nxt = 2;
    for (int c = 0; c < 64; c++) {
        CP_WAIT1();
        __syncthreads();
        if (c + 2 < 64) issue(c + 2, s_nxt);
        CP_COMMIT();

        const uint32_t base = sbase + (uint32_t)s_cur * BUF_BYTES;
#pragma unroll
        for (int ks = 0; ks < 2; ks++) {
            uint32_t ah[4][4], al[4][4], bh[4][2], bl[4][2];
#pragma unroll
            for (int mt = 0; mt < 4; mt++) {
                uint32_t ra = base + (uint32_t)(a_row + mt * 16) * 112
                            + (uint32_t)(ks * 16 + a_kc) * 2;
                LDSM4(ah[mt], ra);
                LDSM4(al[mt], ra + TILE_BYTES);
            }
#pragma unroll
            for (int pr = 0; pr < 2; pr++) {
                uint32_t rb = base + 2 * TILE_BYTES
                            + (uint32_t)(b_row + pr * 16) * 112
                            + (uint32_t)(ks * 16 + b_kc) * 2;
                uint32_t t[4];
                LDSM4(t, rb);
                bh[2 * pr][0] = t[0]; bh[2 * pr][1] = t[1];
                bh[2 * pr + 1][0] = t[2]; bh[2 * pr + 1][1] = t[3];
                LDSM4(t, rb + TILE_BYTES);
                bl[2 * pr][0] = t[0]; bl[2 * pr][1] = t[1];
                bl[2 * pr + 1][0] = t[2]; bl[2 * pr + 1][1] = t[3];
            }
#pragma unroll
            for (int mt = 0; mt < 4; mt++)
#pragma unroll
                for (int nt = 0; nt < 4; nt++) {
                    MMA16816(acc[mt][nt], ah[mt], bh[nt]);
                    MMA16816(acc[mt][nt], ah[mt], bl[nt]);
                    MMA16816(acc[mt][nt], al[mt], bh[nt]);
                }
        }
        s_cur = (s_cur == 2) ? 0 : s_cur + 1;
        s_nxt = (s_nxt == 2) ? 0 : s_nxt + 1;
    }

    // ---- epilogue ----
#pragma unroll
    for (int mt = 0; mt < 4; mt++) {
        const int row = bm + wm + mt * 16 + (lane >> 2);
        const int bi0 = row >> 11, ni0 = row & (SEQ - 1);
        const int r1 = row + 8;
        const int bi1 = r1 >> 11, ni1 = r1 & (SEQ - 1);
#pragma unroll
        for (int nt = 0; nt < 4; nt++) {
            const int col = bn + wn + nt * 8 + (lane & 3) * 2;
            const float a0 = acc[mt][nt][0], a1 = acc[mt][nt][1];
            const float a2 = acc[mt][nt][2], a3 = acc[mt][nt][3];
            if (mode == 1) {
                const int which = col >> 11;
                const int hh = (col >> 7) & (NH - 1);
                const int t = col & (HDIM - 1);
                const size_t i0 = (((size_t)bi0 * NH + hh) * SEQ + ni0) * HDIM + t;
                const size_t i1 = (((size_t)bi1 * NH + hh) * SEQ + ni1) * HDIM + t;
                if (which == 2) {
                    __nv_bfloat162 h01, l01, h23, l23;
                    h01.x = __float2bfloat16(a0);
                    h01.y = __float2bfloat16(a1);
                    l01.x = __float2bfloat16(a0 - __bfloat162float(h01.x));
                    l01.y = __float2bfloat16(a1 - __bfloat162float(h01.y));
                    h23.x = __float2bfloat16(a2);
                    h23.y = __float2bfloat16(a3);
                    l23.x = __float2bfloat16(a2 - __bfloat162float(h23.x));
                    l23.y = __float2bfloat16(a3 - __bfloat162float(h23.y));
                    *(__nv_bfloat162*)(g_vh + i0) = h01;
                    *(__nv_bfloat162*)(g_vl + i0) = l01;
                    *(__nv_bfloat162*)(g_vh + i1) = h23;
                    *(__nv_bfloat162*)(g_vl + i1) = l23;
                } else {
                    float* dst = which ? g_k : g_q;
                    *(float2*)(dst + i0) = make_float2(a0, a1);
                    *(float2*)(dst + i1) = make_float2(a2, a3);
                }
            } else {
                *(float2*)(C + (size_t)row * DIM + col) = make_float2(a0, a1);
                *(float2*)(C + (size_t)r1 * DIM + col)  = make_float2(a2, a3);
            }
        }
    }
}

// ---------------------------------------------------------------------------
// RoPE + bf16 hi/lo split: g_q/g_k fp32 -> g_qh/ql/kh/kl.
// ---------------------------------------------------------------------------
__global__ void rope_split_kernel()
{
    int idx = blockIdx.x * blockDim.x + threadIdx.x;  // BSZ*NH*SEQ*64
    int t = idx & 63;
    int ni = (idx >> 6) & (SEQ - 1);
    int bh = idx >> 17;
    size_t base = ((size_t)bh * SEQ + ni) * HDIM;

    float theta = expf((float)t * -0.14391156831f);  // ln(10000)/64
    float ang = (float)ni * theta;
    float s, c;
    sincosf(ang, &s, &c);

    float q1 = g_q[base + t], q2 = g_q[base + t + 64];
    float k1 = g_k[base + t], k2 = g_k[base + t + 64];
    float qa = q1 * c - q2 * s, qb = q1 * s + q2 * c;
    float ka = k1 * c - k2 * s, kb = k1 * s + k2 * c;

    __nv_bfloat16 h;
    h = __float2bfloat16(qa); g_qh[base + t] = h;
    g_ql[base + t] = __float2bfloat16(qa - __bfloat162float(h));
    h = __float2bfloat16(qb); g_qh[base + t + 64] = h;
    g_ql[base + t + 64] = __float2bfloat16(qb - __bfloat162float(h));
    h = __float2bfloat16(ka); g_kh[base + t] = h;
    g_kl[base + t] = __float2bfloat16(ka - __bfloat162float(h));
    h = __float2bfloat16(kb); g_kh[base + t + 64] = h;
    g_kl[base + t + 64] = __float2bfloat16(kb - __bfloat162float(h));
}

// ---------------------------------------------------------------------------
// Tensor-core poly attention (validated round 6, unchanged).
// ---------------------------------------------------------------------------
#define ASTR 272
#define OQH 0
#define OQL 17408
#define OKH 34816
#define OKL 52224
#define OVH 69632
#define OVL 87040
#define ATT_SMEM 104448

__global__ void __launch_bounds__(128) attn_tc_kernel()
{
    extern __shared__ __align__(16) char sm[];
    const int tid = threadIdx.x, lane = tid & 31, wid = tid >> 5;
    const int q0 = blockIdx.x * 64;
    const int h = blockIdx.y, bi = blockIdx.z;
    const size_t bh = ((size_t)bi * NH + h) * SEQ;
    const uint32_t sb = s2u(sm);
    const int wq = wid * 16;
    const int g = lane >> 2, tig = lane & 3;
    const uint32_t lrow = lane & 15;
    const uint32_t lseg = (lane >> 4) * 16;

    for (int i = tid; i < 64 * 16; i += 128) {
        int r = i >> 4, gg = i & 15;
        size_t ga = (bh + q0 + r) * HDIM + gg * 8;
        *(uint4*)(sm + OQH + r * ASTR + gg * 16) = *(const uint4*)(g_qh + ga);
        *(uint4*)(sm + OQL + r * ASTR + gg * 16) = *(const uint4*)(g_ql + ga);
    }

    float acc[16][4];
#pragma unroll
    for (int i = 0; i < 16; i++)
#pragma unroll
        for (int r = 0; r < 4; r++) acc[i][r] = 0.f;
    float dr = 0.f, dr8 = 0.f;

    const uint32_t qa_base = sb + OQH + (uint32_t)(wq + lrow) * ASTR + lseg;
    const int qg = q0 + wq + g, qg8 = qg + 8;

    for (int j0 = 0; j0 <= q0; j0 += 64) {
        __syncthreads();
        for (int i = tid; i < 64 * 16; i += 128) {
            int r = i >> 4, gg = i & 15;
            size_t ga = (bh + j0 + r) * HDIM + gg * 8;
            uint32_t so = r * ASTR + gg * 16;
            *(uint4*)(sm + OKH + so) = *(const uint4*)(g_kh + ga);
            *(uint4*)(sm + OKL + so) = *(const uint4*)(g_kl + ga);
            *(uint4*)(sm + OVH + so) = *(const uint4*)(g_vh + ga);
            *(uint4*)(sm + OVL + so) = *(const uint4*)(g_vl + ga);
        }
        __syncthreads();

        float c[8][4];
#pragma unroll
        for (int nt = 0; nt < 8; nt++)
#pragma unroll
            for (int r = 0; r < 4; r++) c[nt][r] = 0.f;

#pragma unroll
        for (int kc = 0; kc < 8; kc++) {
            uint32_t ah4[4], al4[4];
            LDSM4(ah4, qa_base + kc * 32);
            LDSM4(al4, qa_base + (OQL - OQH) + kc * 32);
#pragma unroll
            for (int j2 = 0; j2 < 4; j2++) {
                uint32_t rb = sb + OKH + (uint32_t)(j2 * 16 + lrow) * ASTR
                            + kc * 32 + lseg;
                uint32_t kh4[4], kl4[4];
                LDSM4(kh4, rb);
                LDSM4(kl4, rb + (OKL - OKH));
                uint32_t b0h[2] = { kh4[0], kh4[2] }, b1h[2] = { kh4[1], kh4[3] };
                uint32_t b0l[2] = { kl4[0], kl4[2] }, b1l[2] = { kl4[1], kl4[3] };
                MMA16816(c[2 * j2],     ah4, b0h);
                MMA16816(c[2 * j2],     ah4, b0l);
                MMA16816(c[2 * j2],     al4, b0h);
                MMA16816(c[2 * j2 + 1], ah4, b1h);
                MMA16816(c[2 * j2 + 1], ah4, b1l);
                MMA16816(c[2 * j2 + 1], al4, b1h);
            }
        }

        uint32_t sh[4][4], sl[4][4];
        const bool diag = (j0 == q0);
#pragma unroll
        for (int nt = 0; nt < 8; nt++) {
            const int kcol = j0 + nt * 8 + 2 * tig;
            float t2, p0, p1, p2, p3;
            t2 = c[nt][0] * c[nt][0]; p0 = t2 * t2;
            t2 = c[nt][1] * c[nt][1]; p1 = t2 * t2;
            t2 = c[nt][2] * c[nt][2]; p2 = t2 * t2;
            t2 = c[nt][3] * c[nt][3]; p3 = t2 * t2;
            if (diag) {
                if (kcol     > qg)  p0 = 0.f;
                if (kcol + 1 > qg)  p1 = 0.f;
                if (kcol     > qg8) p2 = 0.f;
                if (kcol + 1 > qg8) p3 = 0.f;
            }
            dr  += p0 + p1;
            dr8 += p2 + p3;
            const int kf = nt >> 1, hi2 = (nt & 1) * 2;
            uint32_t ph01 = packbf(p0, p1);
            uint32_t ph23 = packbf(p2, p3);
            __nv_bfloat162 hv01 = *(__nv_bfloat162*)&ph01;
            __nv_bfloat162 hv23 = *(__nv_bfloat162*)&ph23;
            sh[kf][hi2]     = ph01;
            sh[kf][hi2 + 1] = ph23;
            sl[kf][hi2]     = packbf(p0 - __bfloat162float(hv01.x),
                                     p1 - __bfloat162float(hv01.y));
            sl[kf][hi2 + 1] = packbf(p2 - __bfloat162float(hv23.x),
                                     p3 - __bfloat162float(hv23.y));
        }

#pragma unroll
        for (int d2 = 0; d2 < 8; d2++) {
#pragma unroll
            for (int kf = 0; kf < 4; kf++) {
                uint32_t rv = sb + OVH + (uint32_t)(kf * 16 + lrow) * ASTR
                            + d2 * 32 + lseg;
                uint32_t vh4[4], vl4[4];
                LDSM4T(vh4, rv);
                LDSM4T(vl4, rv + (OVL - OVH));
                uint32_t bv0h[2] = { vh4[0], vh4[1] }, bv1h[2] = { vh4[2], vh4[3] };
                uint32_t bv0l[2] = { vl4[0], vl4[1] }, bv1l[2] = { vl4[2], vl4[3] };
                MMA16816(acc[2 * d2],     sh[kf], bv0h);
                MMA16816(acc[2 * d2],     sh[kf], bv0l);
                MMA16816(acc[2 * d2],     sl[kf], bv0h);
                MMA16816(acc[2 * d2 + 1], sh[kf], bv1h);
                MMA16816(acc[2 * d2 + 1], sh[kf], bv1l);
                MMA16816(acc[2 * d2 + 1], sl[kf], bv1h);
            }
        }
    }

    dr  += __shfl_xor_sync(0xFFFFFFFFu, dr, 1);
    dr  += __shfl_xor_sync(0xFFFFFFFFu, dr, 2);
    dr8 += __shfl_xor_sync(0xFFFFFFFFu, dr8, 1);
    dr8 += __shfl_xor_sync(0xFFFFFFFFu, dr8, 2);
    const float inv  = 1.f / fmaxf(dr, 1e-6f);
    const float inv8 = 1.f / fmaxf(dr8, 1e-6f);

    const int n0 = q0 + wq + g;
#pragma unroll
    for (int dg = 0; dg < 16; dg++) {
        const int col = h * HDIM + dg * 8 + 2 * tig;
        float2 v0 = { acc[dg][0] * inv,  acc[dg][1] * inv  };
        float2 v1 = { acc[dg][2] * inv8, acc[dg][3] * inv8 };
        *(float2*)(g_att + ((size_t)bi * SEQ + n0) * DIM + col) = v0;
        *(float2*)(g_att + ((size_t)bi * SEQ + n0 + 8) * DIM + col) = v1;
    }
}

// ---------------------------------------------------------------------------
extern "C" void kernel_launch(void* const* d_in, const int* in_sizes, int n_in,
                              void* d_out, int out_size)
{
    const float* x  = (const float*)d_in[0];
    const float* Wq = (const float*)d_in[1];
    const float* Wk = (const float*)d_in[2];
    const float* Wv = (const float*)d_in[3];
    const float* Wo = (const float*)d_in[4];
    float* out = (float*)d_out;

    float *att;
    __nv_bfloat16 *xh, *xl, *wh, *wl;
    cudaGetSymbolAddress((void**)&att, g_att);
    cudaGetSymbolAddress((void**)&xh, g_xh);
    cudaGetSymbolAddress((void**)&xl, g_xl);
    cudaGetSymbolAddress((void**)&wh, g_wh);
    cudaGetSymbolAddress((void**)&wl, g_wl);

    cudaFuncSetAttribute(mma_gemm_kernel,
                         cudaFuncAttributeMaxDynamicSharedMemorySize, SMEM_DYN);
    cudaFuncSetAttribute(attn_tc_kernel,
                         cudaFuncAttributeMaxDynamicSharedMemorySize, ATT_SMEM);

    const int xblocks = (MTOT * DIM / 4) / 256;   // 8192
    const int wblocks = (DIM * DIM / 4) / 256;    // 4096
    const int WSZ = DIM * DIM;

    // split x and all three projection weights (concatenated)
    split_kernel<<<xblocks, 256>>>(x, xh, xl);
    split_kernel<<<wblocks, 256>>>(Wq, wh, wl);
    split_kernel<<<wblocks, 256>>>(Wk, wh + WSZ, wl + WSZ);
    split_kernel<<<wblocks, 256>>>(Wv, wh + 2 * WSZ, wl + 2 * WSZ);

    // fused QKV GEMM: N = 6144
    mma_gemm_kernel<<<dim3(3 * DIM / 128, MTOT / 128), 256, SMEM_DYN>>>(
        xh, xl, wh, wl, out, 1);

    rope_split_kernel<<<(BSZ * NH * SEQ * 64) / 256, 256>>>();

    attn_tc_kernel<<<dim3(SEQ / 64, NH, BSZ), 128, ATT_SMEM>>>();

    split_kernel<<<xblocks, 256>>>(att, xh, xl);
    split_kernel<<<wblocks, 256>>>(Wo, wh, wl);
    mma_gemm_kernel<<<dim3(DIM / 128, MTOT / 128), 256, SMEM_DYN>>>(
        xh, xl, wh, wl, out, 0);
}